// round 8
// baseline (speedup 1.0000x reference)
#include <cuda_runtime.h>

// Problem constants (fixed by dataset)
#define LP   640
#define LC   128
#define NODE 128
#define HID  32
#define PAIR 128
#define TILE_I 64   // i-rows per block in pair kernel
#define CHUNK 16    // i's per inner chunk (8 float2 acc chains)
#define JPB  2      // j columns per pair block

// Scratch (no allocations allowed -> __device__ globals)
__device__ float g_p[LP * HID];            // LN+Linear of p_embed  [i][c]
__device__ float g_c[LC * HID];            // LN+Linear of c_embed  [j][e]
__device__ float g_Mt[LC * PAIR * HID];    // Mt[j][k][c] = sum_e W3[k,c,e] * c[j,e]

__device__ __forceinline__ float warp_sum(float v) {
#pragma unroll
    for (int o = 16; o; o >>= 1) v += __shfl_xor_sync(0xffffffffu, v, o);
    return v;
}

// packed fp32x2 ops (Blackwell)
__device__ __forceinline__ float2 ffma2(float2 a, float2 b, float2 c) {
    float2 d;
    asm("fma.rn.f32x2 %0, %1, %2, %3;"
        : "=l"(reinterpret_cast<unsigned long long&>(d))
        : "l"(reinterpret_cast<const unsigned long long&>(a)),
          "l"(reinterpret_cast<const unsigned long long&>(b)),
          "l"(reinterpret_cast<const unsigned long long&>(c)));
    return d;
}
__device__ __forceinline__ float2 fmul2(float2 a, float2 b) {
    float2 d;
    asm("mul.rn.f32x2 %0, %1, %2;"
        : "=l"(reinterpret_cast<unsigned long long&>(d))
        : "l"(reinterpret_cast<const unsigned long long&>(a)),
          "l"(reinterpret_cast<const unsigned long long&>(b)));
    return d;
}

// ---------------------------------------------------------------------------
// Kernel A (fused): LayerNorm + Linear(NODE->HID), TWO rows per block.
// grid = (LP+LC)/2 = 384, block = 256 (two independent 128-thread groups).
// Interleaves the two rows' reduction chains to hide SHFL latency.
// ---------------------------------------------------------------------------
__global__ void __launch_bounds__(256)
ln_linear_all(const float* __restrict__ p_embed, const float* __restrict__ c_embed,
              const float* __restrict__ ln_p_w, const float* __restrict__ ln_p_b,
              const float* __restrict__ ln_c_w, const float* __restrict__ ln_c_b,
              const float* __restrict__ W_p,   const float* __restrict__ b_p,
              const float* __restrict__ W_c,   const float* __restrict__ b_c)
{
    int g = threadIdx.x >> 7;              // row-group 0/1
    int t = threadIdx.x & 127;             // 0..127 within group
    int r = blockIdx.x * 2 + g;
    bool isp = (r < LP);
    int rr = isp ? r : r - LP;
    const float* emb  = isp ? (p_embed + (size_t)rr * NODE) : (c_embed + (size_t)rr * NODE);
    const float* lnw  = isp ? ln_p_w : ln_c_w;
    const float* lnb  = isp ? ln_p_b : ln_c_b;
    const float* W    = isp ? W_p : W_c;
    const float* bias = isp ? b_p : b_c;
    float* dst        = (isp ? g_p : g_c) + (size_t)rr * HID;

    __shared__ float part1[2][4], part2[2][4];
    __shared__ __align__(16) float s[2][NODE];

    float x = emb[t];
    float ws = warp_sum(x);
    if ((t & 31) == 0) part1[g][t >> 5] = ws;
    __syncthreads();
    float mean = (part1[g][0] + part1[g][1] + part1[g][2] + part1[g][3]) * (1.0f / NODE);
    float d = x - mean;
    float w2 = warp_sum(d * d);
    if ((t & 31) == 0) part2[g][t >> 5] = w2;
    __syncthreads();
    float var = (part2[g][0] + part2[g][1] + part2[g][2] + part2[g][3]) * (1.0f / NODE);
    s[g][t] = d * rsqrtf(var + 1e-5f) * lnw[t] + lnb[t];
    __syncthreads();

    int w = t >> 5, lane = t & 31;
    float4 sv = ((const float4*)s[g])[lane];
#pragma unroll
    for (int rrh = 0; rrh < 8; rrh++) {
        int h = w * 8 + rrh;
        float4 wv = ((const float4*)(W + (size_t)h * NODE))[lane];
        float a = wv.x * sv.x + wv.y * sv.y + wv.z * sv.z + wv.w * sv.w;
        a = warp_sum(a);
        if (lane == 0) dst[h] = a + bias[h];
    }
}

// ---------------------------------------------------------------------------
// Kernel B: Mt[j][k][c] = sum_e W_out[k, c*HID + e] * g_c[j, e]
// grid = (LC/8, HID/2), block = 128 (thread = k). W_out staged coalesced.
// ---------------------------------------------------------------------------
__global__ void __launch_bounds__(128)
make_M_kernel(const float* __restrict__ Wout)
{
    int k  = threadIdx.x;          // 0..127
    int j0 = blockIdx.x * 8;
    int cb = blockIdx.y;           // c-pair index: global c = cb*2 + {0,1}

    __shared__ float ws[128][67];  // ws[k][c*32+e], padded
    __shared__ float cs[8][HID];

    {
        const float* base = Wout + (size_t)cb * 64;
#pragma unroll
        for (int q = 0; q < 16; q++) {
            int lin4 = q * 128 + k;        // 0..2047 float4s
            int kk   = lin4 >> 4;          // 16 float4 per k
            int x4   = lin4 & 15;
            float4 v = *(const float4*)(base + (size_t)kk * 1024 + x4 * 4);
            ws[kk][x4 * 4 + 0] = v.x;
            ws[kk][x4 * 4 + 1] = v.y;
            ws[kk][x4 * 4 + 2] = v.z;
            ws[kk][x4 * 4 + 3] = v.w;
        }
    }
    for (int idx = k; idx < 8 * HID; idx += 128)
        cs[idx >> 5][idx & 31] = g_c[(size_t)(j0 + (idx >> 5)) * HID + (idx & 31)];
    __syncthreads();

    float acc[8][2];
#pragma unroll
    for (int jj = 0; jj < 8; jj++) { acc[jj][0] = 0.f; acc[jj][1] = 0.f; }

#pragma unroll
    for (int e = 0; e < HID; e++) {
        float w0 = ws[k][e];
        float w1 = ws[k][32 + e];
#pragma unroll
        for (int jj = 0; jj < 8; jj++) {
            float ce = cs[jj][e];
            acc[jj][0] += w0 * ce;
            acc[jj][1] += w1 * ce;
        }
    }
#pragma unroll
    for (int jj = 0; jj < 8; jj++) {
        float2 v = make_float2(acc[jj][0], acc[jj][1]);
        *(float2*)(g_Mt + ((size_t)(j0 + jj) * PAIR + k) * HID + cb * 2) = v;
    }
}

// ---------------------------------------------------------------------------
// Kernel C (main): out[i,j,k] = (sum_c p[i,c]*Mt[j,c,k] + b_out[k]) * mask
// grid = (LP/TILE_I, LC/JPB), block = 256.
// Chunks of 16 i's -> 8 independent float2 acc chains per thread.
// Per c: 4 LDS.128 (broadcast) + 8 FFMA2.
// ---------------------------------------------------------------------------
__global__ void __launch_bounds__(256)
pair_kernel(const float* __restrict__ b_out,
            const int* __restrict__ pmask,
            const int* __restrict__ cmask,
            float* __restrict__ out,
            float* __restrict__ outm,   // mask region or nullptr
            int has_mask)
{
    int tid = threadIdx.x;
    int jl  = tid >> 7;                 // 0..1
    int k   = tid & 127;                // 0..127
    int j   = blockIdx.y * JPB + jl;
    int i0  = blockIdx.x * TILE_I;

    // md[c] = (Mt[j][k][c], Mt[j][k][c])
    float2 md[HID];
    {
        const float4* src = (const float4*)(g_Mt + ((size_t)j * PAIR + k) * HID);
#pragma unroll
        for (int q = 0; q < 8; q++) {
            float4 v = src[q];
            md[4*q+0] = make_float2(v.x, v.x);
            md[4*q+1] = make_float2(v.y, v.y);
            md[4*q+2] = make_float2(v.z, v.z);
            md[4*q+3] = make_float2(v.w, v.w);
        }
    }

    __shared__ float  pT[HID][68];          // pT[c][ii], padded rows (272B)
    __shared__ float2 pmc[JPB][TILE_I / 2]; // (pm[i]*cm_j, pm[i+1]*cm_j)

    {
        int c  = tid & 31;
        int ig = tid >> 5;
#pragma unroll
        for (int base = 0; base < TILE_I; base += 8) {
            int ii = base + ig;
            pT[c][ii] = g_p[(size_t)(i0 + ii) * HID + c];
        }
    }
    if (tid < JPB * (TILE_I / 2)) {
        int jl2 = tid / (TILE_I / 2);
        int t   = tid % (TILE_I / 2);
        float cm = cmask[blockIdx.y * JPB + jl2] ? 1.0f : 0.0f;
        float a = pmask[i0 + 2*t]     ? cm : 0.0f;
        float b = pmask[i0 + 2*t + 1] ? cm : 0.0f;
        pmc[jl2][t] = make_float2(a, b);
    }
    // appended inter_mask: 640 blocks x 128 entries = LP*LC
    if (has_mask && jl == 0) {
        int bl  = blockIdx.y * gridDim.x + blockIdx.x;   // 0..639
        int idx = bl * 128 + k;
        int im  = idx >> 7, jm = idx & 127;
        outm[idx] = (pmask[im] && cmask[jm]) ? 1.0f : 0.0f;
    }
    __syncthreads();

    float bk = b_out[k];
    float2 binit = make_float2(bk, bk);
    float* outbase = out + (size_t)i0 * (LC * PAIR) + (size_t)j * PAIR + k;

#pragma unroll 1
    for (int ch = 0; ch < TILE_I / CHUNK; ch++) {
        int li = ch * CHUNK;
        float2 acc0 = binit, acc1 = binit, acc2 = binit, acc3 = binit;
        float2 acc4 = binit, acc5 = binit, acc6 = binit, acc7 = binit;
#pragma unroll
        for (int c = 0; c < HID; c++) {
            float4 a = *(const float4*)&pT[c][li];
            float4 b = *(const float4*)&pT[c][li + 4];
            float4 d = *(const float4*)&pT[c][li + 8];
            float4 e = *(const float4*)&pT[c][li + 12];
            acc0 = ffma2(md[c], make_float2(a.x, a.y), acc0);
            acc1 = ffma2(md[c], make_float2(a.z, a.w), acc1);
            acc2 = ffma2(md[c], make_float2(b.x, b.y), acc2);
            acc3 = ffma2(md[c], make_float2(b.z, b.w), acc3);
            acc4 = ffma2(md[c], make_float2(d.x, d.y), acc4);
            acc5 = ffma2(md[c], make_float2(d.z, d.w), acc5);
            acc6 = ffma2(md[c], make_float2(e.x, e.y), acc6);
            acc7 = ffma2(md[c], make_float2(e.z, e.w), acc7);
        }
        int lh = li / 2;
        acc0 = fmul2(acc0, pmc[jl][lh + 0]);
        acc1 = fmul2(acc1, pmc[jl][lh + 1]);
        acc2 = fmul2(acc2, pmc[jl][lh + 2]);
        acc3 = fmul2(acc3, pmc[jl][lh + 3]);
        acc4 = fmul2(acc4, pmc[jl][lh + 4]);
        acc5 = fmul2(acc5, pmc[jl][lh + 5]);
        acc6 = fmul2(acc6, pmc[jl][lh + 6]);
        acc7 = fmul2(acc7, pmc[jl][lh + 7]);
        size_t rs = (size_t)(LC * PAIR);
        float* ob = outbase + (size_t)li * rs;
        ob[0*rs]  = acc0.x;  ob[1*rs]  = acc0.y;
        ob[2*rs]  = acc1.x;  ob[3*rs]  = acc1.y;
        ob[4*rs]  = acc2.x;  ob[5*rs]  = acc2.y;
        ob[6*rs]  = acc3.x;  ob[7*rs]  = acc3.y;
        ob[8*rs]  = acc4.x;  ob[9*rs]  = acc4.y;
        ob[10*rs] = acc5.x;  ob[11*rs] = acc5.y;
        ob[12*rs] = acc6.x;  ob[13*rs] = acc6.y;
        ob[14*rs] = acc7.x;  ob[15*rs] = acc7.y;
    }
}

extern "C" void kernel_launch(void* const* d_in, const int* in_sizes, int n_in,
                              void* d_out, int out_size)
{
    const float* p_embed = (const float*)d_in[0];
    const float* c_embed = (const float*)d_in[1];
    const int*   p_mask  = (const int*)d_in[2];
    const int*   c_mask  = (const int*)d_in[3];
    const float* ln_p_w  = (const float*)d_in[4];
    const float* ln_p_b  = (const float*)d_in[5];
    const float* ln_c_w  = (const float*)d_in[6];
    const float* ln_c_b  = (const float*)d_in[7];
    const float* W_p     = (const float*)d_in[8];
    const float* b_p     = (const float*)d_in[9];
    const float* W_c     = (const float*)d_in[10];
    const float* b_c     = (const float*)d_in[11];
    const float* W_out   = (const float*)d_in[12];
    const float* b_out   = (const float*)d_in[13];
    float* out = (float*)d_out;

    ln_linear_all<<<(LP + LC) / 2, 256>>>(p_embed, c_embed, ln_p_w, ln_p_b,
                                          ln_c_w, ln_c_b, W_p, b_p, W_c, b_c);

    dim3 gB(LC / 8, HID / 2);
    make_M_kernel<<<gB, 128>>>(W_out);

    long long main_elems = (long long)LP * LC * PAIR;
    int has_mask = ((long long)out_size >= main_elems + (long long)LP * LC) ? 1 : 0;
    float* outm = out + main_elems;

    dim3 gC(LP / TILE_I, LC / JPB);
    pair_kernel<<<gC, 256>>>(b_out, p_mask, c_mask, out, outm, has_mask);
}

// round 13
// speedup vs baseline: 1.5931x; 1.5931x over previous
#include <cuda_runtime.h>

// Problem constants (fixed by dataset)
#define LP   640
#define LC   128
#define NODE 128
#define HID  32
#define PAIR 128
#define TILE_I 64   // i-rows per block in pair kernel
#define JPB  2      // j columns per pair block

// Scratch (no allocations allowed -> __device__ globals)
__device__ float g_p[LP * HID];            // LN+Linear of p_embed  [i][c]
__device__ float g_c[LC * HID];            // LN+Linear of c_embed  [j][e]
__device__ float g_Mt[LC * PAIR * HID];    // Mt[j][k][c] = sum_e W3[k,c,e] * c[j,e]

__device__ __forceinline__ float warp_sum(float v) {
#pragma unroll
    for (int o = 16; o; o >>= 1) v += __shfl_xor_sync(0xffffffffu, v, o);
    return v;
}

// packed fp32x2 ops (Blackwell; plain sm_103 PTX, no 'a'-only features)
__device__ __forceinline__ float2 ffma2(float2 a, float2 b, float2 c) {
    float2 d;
    asm("fma.rn.f32x2 %0, %1, %2, %3;"
        : "=l"(reinterpret_cast<unsigned long long&>(d))
        : "l"(reinterpret_cast<const unsigned long long&>(a)),
          "l"(reinterpret_cast<const unsigned long long&>(b)),
          "l"(reinterpret_cast<const unsigned long long&>(c)));
    return d;
}
__device__ __forceinline__ float2 fmul2(float2 a, float2 b) {
    float2 d;
    asm("mul.rn.f32x2 %0, %1, %2;"
        : "=l"(reinterpret_cast<unsigned long long&>(d))
        : "l"(reinterpret_cast<const unsigned long long&>(a)),
          "l"(reinterpret_cast<const unsigned long long&>(b)));
    return d;
}

// ---------------------------------------------------------------------------
// Kernel A (fused): LayerNorm + Linear(NODE->HID) for BOTH p (rows 0..639)
// and c (rows 640..767). grid = LP+LC, block = 128.
// Single-pass LN stats (sum + sumsq reduced in parallel), then the Linear
// phase with all 8 W rows prefetched (MLP=8) before the reduction rounds.
// ---------------------------------------------------------------------------
__global__ void __launch_bounds__(128)
ln_linear_all(const float* __restrict__ p_embed, const float* __restrict__ c_embed,
              const float* __restrict__ ln_p_w, const float* __restrict__ ln_p_b,
              const float* __restrict__ ln_c_w, const float* __restrict__ ln_c_b,
              const float* __restrict__ W_p,   const float* __restrict__ b_p,
              const float* __restrict__ W_c,   const float* __restrict__ b_c)
{
    int r = blockIdx.x;
    bool isp = (r < LP);
    int rr = isp ? r : r - LP;
    const float* emb  = isp ? (p_embed + (size_t)rr * NODE) : (c_embed + (size_t)rr * NODE);
    const float* lnw  = isp ? ln_p_w : ln_c_w;
    const float* lnb  = isp ? ln_p_b : ln_c_b;
    const float* W    = isp ? W_p : W_c;
    const float* bias = isp ? b_p : b_c;
    float* dst        = (isp ? g_p : g_c) + (size_t)rr * HID;

    int t = threadIdx.x;
    __shared__ float part1[4], part2[4];
    __shared__ __align__(16) float s[NODE];

    // one-pass statistics: sum and sumsq reduced with interleaved SHFL chains
    float x  = emb[t];
    float s1 = warp_sum(x);
    float s2 = warp_sum(x * x);
    if ((t & 31) == 0) { part1[t >> 5] = s1; part2[t >> 5] = s2; }
    __syncthreads();
    float mean = (part1[0] + part1[1] + part1[2] + part1[3]) * (1.0f / NODE);
    float ex2  = (part2[0] + part2[1] + part2[2] + part2[3]) * (1.0f / NODE);
    float var  = ex2 - mean * mean;
    float d    = x - mean;
    s[t] = d * rsqrtf(var + 1e-5f) * lnw[t] + lnb[t];
    __syncthreads();

    int w = t >> 5, lane = t & 31;
    float4 sv = ((const float4*)s)[lane];

    // prefetch all 8 W rows for this warp (coalesced float4, MLP=8)
    float4 wv[8];
#pragma unroll
    for (int rrh = 0; rrh < 8; rrh++)
        wv[rrh] = ((const float4*)(W + (size_t)(w * 8 + rrh) * NODE))[lane];

#pragma unroll
    for (int rrh = 0; rrh < 8; rrh++) {
        int h = w * 8 + rrh;
        float a = wv[rrh].x * sv.x + wv[rrh].y * sv.y
                + wv[rrh].z * sv.z + wv[rrh].w * sv.w;
        a = warp_sum(a);
        if (lane == 0) dst[h] = a + bias[h];
    }
}

// ---------------------------------------------------------------------------
// Kernel B: Mt[j][k][c] = sum_e W_out[k, c*HID + e] * g_c[j, e]
// grid = (LC/8, HID/2), block = 128 (thread = k). W_out staged coalesced,
// padded smem rows -> conflict-free compute reads. float2 stores.
// ---------------------------------------------------------------------------
__global__ void __launch_bounds__(128)
make_M_kernel(const float* __restrict__ Wout)
{
    int k  = threadIdx.x;          // 0..127
    int j0 = blockIdx.x * 8;
    int cb = blockIdx.y;           // c-pair index: global c = cb*2 + {0,1}

    __shared__ float ws[128][67];  // ws[k][c*32+e], padded
    __shared__ float cs[8][HID];

    {
        const float* base = Wout + (size_t)cb * 64;
#pragma unroll
        for (int q = 0; q < 16; q++) {
            int lin4 = q * 128 + k;        // 0..2047 float4s
            int kk   = lin4 >> 4;          // 16 float4 per k
            int x4   = lin4 & 15;
            float4 v = *(const float4*)(base + (size_t)kk * 1024 + x4 * 4);
            ws[kk][x4 * 4 + 0] = v.x;
            ws[kk][x4 * 4 + 1] = v.y;
            ws[kk][x4 * 4 + 2] = v.z;
            ws[kk][x4 * 4 + 3] = v.w;
        }
    }
    for (int idx = k; idx < 8 * HID; idx += 128)
        cs[idx >> 5][idx & 31] = g_c[(size_t)(j0 + (idx >> 5)) * HID + (idx & 31)];
    __syncthreads();

    float acc[8][2];
#pragma unroll
    for (int jj = 0; jj < 8; jj++) { acc[jj][0] = 0.f; acc[jj][1] = 0.f; }

#pragma unroll
    for (int e = 0; e < HID; e++) {
        float w0 = ws[k][e];
        float w1 = ws[k][32 + e];
#pragma unroll
        for (int jj = 0; jj < 8; jj++) {
            float ce = cs[jj][e];
            acc[jj][0] += w0 * ce;
            acc[jj][1] += w1 * ce;
        }
    }
#pragma unroll
    for (int jj = 0; jj < 8; jj++) {
        float2 v = make_float2(acc[jj][0], acc[jj][1]);
        *(float2*)(g_Mt + ((size_t)(j0 + jj) * PAIR + k) * HID + cb * 2) = v;
    }
}

// ---------------------------------------------------------------------------
// Kernel C (main): out[i,j,k] = (sum_c p[i,c]*Mt[j,c,k] + b_out[k]) * mask
// grid = (LP/TILE_I, LC/JPB), block = 256.  (round-7 proven version)
// Thread: jl = tid>>7, k = tid&127. md[c] duplicated float2 in regs;
// per c: 2 LDS.128 (broadcast) + 4 FFMA2 over an 8-i chunk.
// Also writes the appended inter_mask region.
// ---------------------------------------------------------------------------
__global__ void __launch_bounds__(256)
pair_kernel(const float* __restrict__ b_out,
            const int* __restrict__ pmask,
            const int* __restrict__ cmask,
            float* __restrict__ out,
            float* __restrict__ outm,   // mask region or nullptr
            int has_mask)
{
    int tid = threadIdx.x;
    int jl  = tid >> 7;                 // 0..1
    int k   = tid & 127;                // 0..127
    int j   = blockIdx.y * JPB + jl;
    int i0  = blockIdx.x * TILE_I;

    // md[c] = (Mt[j][k][c], Mt[j][k][c])
    float2 md[HID];
    {
        const float4* src = (const float4*)(g_Mt + ((size_t)j * PAIR + k) * HID);
#pragma unroll
        for (int q = 0; q < 8; q++) {
            float4 v = src[q];
            md[4*q+0] = make_float2(v.x, v.x);
            md[4*q+1] = make_float2(v.y, v.y);
            md[4*q+2] = make_float2(v.z, v.z);
            md[4*q+3] = make_float2(v.w, v.w);
        }
    }

    __shared__ float  pT[HID][68];          // pT[c][ii], padded rows (272B)
    __shared__ float2 pmc[JPB][TILE_I / 2]; // (pm[i]*cm_j, pm[i+1]*cm_j)

    {
        int c  = tid & 31;
        int ig = tid >> 5;
#pragma unroll
        for (int base = 0; base < TILE_I; base += 8) {
            int ii = base + ig;
            pT[c][ii] = g_p[(size_t)(i0 + ii) * HID + c];
        }
    }
    if (tid < JPB * (TILE_I / 2)) {
        int jl2 = tid / (TILE_I / 2);
        int t   = tid % (TILE_I / 2);
        float cm = cmask[blockIdx.y * JPB + jl2] ? 1.0f : 0.0f;
        float a = pmask[i0 + 2*t]     ? cm : 0.0f;
        float b = pmask[i0 + 2*t + 1] ? cm : 0.0f;
        pmc[jl2][t] = make_float2(a, b);
    }
    // appended inter_mask: 640 blocks x 128 entries = LP*LC
    if (has_mask && jl == 0) {
        int bl  = blockIdx.y * gridDim.x + blockIdx.x;   // 0..639
        int idx = bl * 128 + k;
        int im  = idx >> 7, jm = idx & 127;
        outm[idx] = (pmask[im] && cmask[jm]) ? 1.0f : 0.0f;
    }
    __syncthreads();

    float bk = b_out[k];
    float2 binit = make_float2(bk, bk);
    float* outbase = out + (size_t)i0 * (LC * PAIR) + (size_t)j * PAIR + k;

#pragma unroll 1
    for (int ch = 0; ch < TILE_I / 8; ch++) {
        int li = ch * 8;
        float2 acc0 = binit, acc1 = binit, acc2 = binit, acc3 = binit;
#pragma unroll
        for (int c = 0; c < HID; c++) {
            float4 a = *(const float4*)&pT[c][li];
            float4 b = *(const float4*)&pT[c][li + 4];
            acc0 = ffma2(md[c], make_float2(a.x, a.y), acc0);
            acc1 = ffma2(md[c], make_float2(a.z, a.w), acc1);
            acc2 = ffma2(md[c], make_float2(b.x, b.y), acc2);
            acc3 = ffma2(md[c], make_float2(b.z, b.w), acc3);
        }
        acc0 = fmul2(acc0, pmc[jl][li/2 + 0]);
        acc1 = fmul2(acc1, pmc[jl][li/2 + 1]);
        acc2 = fmul2(acc2, pmc[jl][li/2 + 2]);
        acc3 = fmul2(acc3, pmc[jl][li/2 + 3]);
        outbase[(size_t)(li + 0) * (LC * PAIR)] = acc0.x;
        outbase[(size_t)(li + 1) * (LC * PAIR)] = acc0.y;
        outbase[(size_t)(li + 2) * (LC * PAIR)] = acc1.x;
        outbase[(size_t)(li + 3) * (LC * PAIR)] = acc1.y;
        outbase[(size_t)(li + 4) * (LC * PAIR)] = acc2.x;
        outbase[(size_t)(li + 5) * (LC * PAIR)] = acc2.y;
        outbase[(size_t)(li + 6) * (LC * PAIR)] = acc3.x;
        outbase[(size_t)(li + 7) * (LC * PAIR)] = acc3.y;
    }
}

extern "C" void kernel_launch(void* const* d_in, const int* in_sizes, int n_in,
                              void* d_out, int out_size)
{
    const float* p_embed = (const float*)d_in[0];
    const float* c_embed = (const float*)d_in[1];
    const int*   p_mask  = (const int*)d_in[2];
    const int*   c_mask  = (const int*)d_in[3];
    const float* ln_p_w  = (const float*)d_in[4];
    const float* ln_p_b  = (const float*)d_in[5];
    const float* ln_c_w  = (const float*)d_in[6];
    const float* ln_c_b  = (const float*)d_in[7];
    const float* W_p     = (const float*)d_in[8];
    const float* b_p     = (const float*)d_in[9];
    const float* W_c     = (const float*)d_in[10];
    const float* b_c     = (const float*)d_in[11];
    const float* W_out   = (const float*)d_in[12];
    const float* b_out   = (const float*)d_in[13];
    float* out = (float*)d_out;

    ln_linear_all<<<LP + LC, 128>>>(p_embed, c_embed, ln_p_w, ln_p_b,
                                    ln_c_w, ln_c_b, W_p, b_p, W_c, b_c);

    dim3 gB(LC / 8, HID / 2);
    make_M_kernel<<<gB, 128>>>(W_out);

    long long main_elems = (long long)LP * LC * PAIR;
    int has_mask = ((long long)out_size >= main_elems + (long long)LP * LC) ? 1 : 0;
    float* outm = out + main_elems;

    dim3 gC(LP / TILE_I, LC / JPB);
    pair_kernel<<<gC, 256>>>(b_out, p_mask, c_mask, out, outm, has_mask);
}